// round 7
// baseline (speedup 1.0000x reference)
#include <cuda_runtime.h>

typedef unsigned long long u64;

// ---------------- packed f32x2 helpers (Blackwell FFMA2) ----------------
__device__ __forceinline__ u64 pack2(float a, float b) {
    u64 r; asm("mov.b64 %0, {%1, %2};" : "=l"(r) : "f"(a), "f"(b)); return r;
}
__device__ __forceinline__ u64 pack1(float a) { return pack2(a, a); }
__device__ __forceinline__ void unpack2(u64 v, float& a, float& b) {
    asm("mov.b64 {%0, %1}, %2;" : "=f"(a), "=f"(b) : "l"(v));
}
__device__ __forceinline__ u64 fma2(u64 a, u64 b, u64 c) {
    u64 d; asm("fma.rn.f32x2 %0, %1, %2, %3;" : "=l"(d) : "l"(a), "l"(b), "l"(c));
    return d;
}
__device__ __forceinline__ u64 relu2(u64 v) {
    float a, b; unpack2(v, a, b);
    a = fmaxf(a, 0.0f); b = fmaxf(b, 0.0f);
    return pack2(a, b);
}

// ---------------- constants ----------------
#define NTHREADS 128
#define ROWS_PER_THREAD 8
#define PAIRS 4
static constexpr int BATCH = 2097152;
static constexpr int CHUNK = BATCH / ROWS_PER_THREAD;  // 262144

// ---------------- padded weight table (u64 indices), bias embedded -------
// stage1 fused: 5 rows, stride 10: [w0..w7, b, pad]       [0,50)
// W2..W4:       5 rows, stride 6:  [w0..w4, b]            [50,80) [80,110) [110,140)
// W5:           4 rows, stride 6:  [w0..w4, b]            [140,164)
#define OFF_FW   0
#define OFF_W2   50
#define OFF_W3   80
#define OFF_W4   110
#define OFF_W5   140
#define W_TOTAL  164

// table pre-packed as duplicated-halves u64 (ready for fma.rn.f32x2)
__device__ u64 g_wp[W_TOTAL];

// ---------------- prep: fuse layer0 into layer1, build packed table ------
// relu(W1 (W0 x + b0) + b1) = relu((W1 W0) x + (W1 b0 + b1))
__global__ void prep_kernel(const float* __restrict__ W0, const float* __restrict__ b0,
                            const float* __restrict__ W1, const float* __restrict__ b1,
                            const float* __restrict__ W2, const float* __restrict__ b2,
                            const float* __restrict__ W3, const float* __restrict__ b3,
                            const float* __restrict__ W4, const float* __restrict__ b4,
                            const float* __restrict__ W5, const float* __restrict__ b5) {
    const int t = threadIdx.x;
    if (t < W_TOTAL) {
        float v;
        if (t < 50) {
            int o = t / 10, k = t % 10;
            if (k < 8) {
                float s = 0.0f;
#pragma unroll
                for (int h = 0; h < 5; h++) s += W1[o * 5 + h] * W0[h * 8 + k];
                v = s;
            } else if (k == 8) {
                float s = b1[o];
#pragma unroll
                for (int h = 0; h < 5; h++) s += W1[o * 5 + h] * b0[h];
                v = s;
            } else {
                v = 0.0f;
            }
        } else if (t < 80) {
            int i = t - OFF_W2, o = i / 6, k = i % 6;
            v = (k < 5) ? W2[o * 5 + k] : b2[o];
        } else if (t < 110) {
            int i = t - OFF_W3, o = i / 6, k = i % 6;
            v = (k < 5) ? W3[o * 5 + k] : b3[o];
        } else if (t < 140) {
            int i = t - OFF_W4, o = i / 6, k = i % 6;
            v = (k < 5) ? W4[o * 5 + k] : b4[o];
        } else {
            int i = t - OFF_W5, o = i / 6, k = i % 6;
            v = (k < 5) ? W5[o * 5 + k] : b5[o];
        }
        g_wp[t] = pack1(v);
    }
    __threadfence();
    __syncthreads();
    // signal dependent grid launch (PDL); memory above is visible to waiters
    asm volatile("griddepcontrol.launch_dependents;" ::: "memory");
}

// stage-1 half-pass: consume 2 pairs (4 rows) of raw inputs, write a[pbase..pbase+1][5].
// xr layout per sub-pair pp: {rowA.lo, rowA.hi, rowB.lo, rowB.hi} at xr[4*pp ..]
__device__ __forceinline__ void stage1_half(u64 a[PAIRS][5], const u64* sw,
                                            const float4 xr[8], int pbase) {
    u64 xv[2][8];
#pragma unroll
    for (int pp = 0; pp < 2; pp++) {
        const float4 a0 = xr[4 * pp + 0], a1 = xr[4 * pp + 1];
        const float4 c0 = xr[4 * pp + 2], c1 = xr[4 * pp + 3];
        xv[pp][0] = pack2(a0.x, c0.x); xv[pp][1] = pack2(a0.y, c0.y);
        xv[pp][2] = pack2(a0.z, c0.z); xv[pp][3] = pack2(a0.w, c0.w);
        xv[pp][4] = pack2(a1.x, c1.x); xv[pp][5] = pack2(a1.y, c1.y);
        xv[pp][6] = pack2(a1.z, c1.z); xv[pp][7] = pack2(a1.w, c1.w);
    }
#pragma unroll
    for (int o = 0; o < 5; o++) {
        ulonglong2 wa = *reinterpret_cast<const ulonglong2*>(sw + OFF_FW + o * 10);
        ulonglong2 wb = *reinterpret_cast<const ulonglong2*>(sw + OFF_FW + o * 10 + 2);
        ulonglong2 wc = *reinterpret_cast<const ulonglong2*>(sw + OFF_FW + o * 10 + 4);
        ulonglong2 wd = *reinterpret_cast<const ulonglong2*>(sw + OFF_FW + o * 10 + 6);
        ulonglong2 we = *reinterpret_cast<const ulonglong2*>(sw + OFF_FW + o * 10 + 8);
#pragma unroll
        for (int pp = 0; pp < 2; pp++) {
            u64 acc = we.x;  // bias
            acc = fma2(xv[pp][0], wa.x, acc);
            acc = fma2(xv[pp][1], wa.y, acc);
            acc = fma2(xv[pp][2], wb.x, acc);
            acc = fma2(xv[pp][3], wb.y, acc);
            acc = fma2(xv[pp][4], wc.x, acc);
            acc = fma2(xv[pp][5], wc.y, acc);
            acc = fma2(xv[pp][6], wd.x, acc);
            acc = fma2(xv[pp][7], wd.y, acc);
            a[pbase + pp][o] = relu2(acc);
        }
    }
}

// one hidden stage (5 -> relu(5)): 3x LDS.128 per neuron row (weights+bias),
// each row applied to all 4 pairs
__device__ __forceinline__ void hidden_stage(u64 a[PAIRS][5], const u64* sw, int woff) {
    u64 h[PAIRS][5];
#pragma unroll
    for (int o = 0; o < 5; o++) {
        ulonglong2 wa = *reinterpret_cast<const ulonglong2*>(sw + woff + o * 6);
        ulonglong2 wb = *reinterpret_cast<const ulonglong2*>(sw + woff + o * 6 + 2);
        ulonglong2 wc = *reinterpret_cast<const ulonglong2*>(sw + woff + o * 6 + 4);
#pragma unroll
        for (int p = 0; p < PAIRS; p++) {
            u64 acc = wc.y;  // bias
            acc = fma2(a[p][0], wa.x, acc);
            acc = fma2(a[p][1], wa.y, acc);
            acc = fma2(a[p][2], wb.x, acc);
            acc = fma2(a[p][3], wb.y, acc);
            acc = fma2(a[p][4], wc.x, acc);
            h[p][o] = relu2(acc);
        }
    }
#pragma unroll
    for (int p = 0; p < PAIRS; p++)
#pragma unroll
        for (int o = 0; o < 5; o++) a[p][o] = h[p][o];
}

__global__ __launch_bounds__(NTHREADS, 4) void mlp_kernel(
    const float4* __restrict__ x, float4* __restrict__ out) {
    __shared__ __align__(16) u64 sw[W_TOTAL];
    const int t = threadIdx.x;
    const int idx = blockIdx.x * NTHREADS + t;  // 0..CHUNK-1
    const float4* xp = x + 2u * (unsigned)idx;

    // front-batch first half inputs (rows 0..3) — independent of prep output
    float4 xA[8];
#pragma unroll
    for (int r = 0; r < 4; r++) {
        const float4* xr = xp + (size_t)r * (2 * CHUNK);
        xA[2 * r]     = __ldg(xr);
        xA[2 * r + 1] = __ldg(xr + 1);
    }

    // PDL: wait for prep kernel's packed table, copy to shared
    asm volatile("griddepcontrol.wait;" ::: "memory");
    if (t < W_TOTAL) sw[t] = g_wp[t];
    if (t + NTHREADS < W_TOTAL) sw[t + NTHREADS] = g_wp[t + NTHREADS];
    __syncthreads();

    // prefetch second half inputs (rows 4..7) while stage1A computes
    float4 xB[8];
#pragma unroll
    for (int r = 0; r < 4; r++) {
        const float4* xr = xp + (size_t)(r + 4) * (2 * CHUNK);
        xB[2 * r]     = __ldg(xr);
        xB[2 * r + 1] = __ldg(xr + 1);
    }

    // ---- stage 1: fused layer01 (8 -> relu(5)), two half-passes ----
    u64 a[PAIRS][5];
    stage1_half(a, sw, xA, 0);
    stage1_half(a, sw, xB, 2);

    // ---- stages 2..4: hidden layers ----
    hidden_stage(a, sw, OFF_W2);
    hidden_stage(a, sw, OFF_W3);
    hidden_stage(a, sw, OFF_W4);

    // ---- stage 5: output layer (5 -> relu(4)) + streaming store ----
    float res[ROWS_PER_THREAD][4];
#pragma unroll
    for (int o = 0; o < 4; o++) {
        ulonglong2 wa = *reinterpret_cast<const ulonglong2*>(sw + OFF_W5 + o * 6);
        ulonglong2 wb = *reinterpret_cast<const ulonglong2*>(sw + OFF_W5 + o * 6 + 2);
        ulonglong2 wc = *reinterpret_cast<const ulonglong2*>(sw + OFF_W5 + o * 6 + 4);
#pragma unroll
        for (int p = 0; p < PAIRS; p++) {
            u64 acc = wc.y;  // bias
            acc = fma2(a[p][0], wa.x, acc);
            acc = fma2(a[p][1], wa.y, acc);
            acc = fma2(a[p][2], wb.x, acc);
            acc = fma2(a[p][3], wb.y, acc);
            acc = fma2(a[p][4], wc.x, acc);
            acc = relu2(acc);
            unpack2(acc, res[2 * p][o], res[2 * p + 1][o]);
        }
    }
    float4* op = out + idx;
#pragma unroll
    for (int r = 0; r < ROWS_PER_THREAD; r++) {
        __stcs(op + (size_t)r * CHUNK,
               make_float4(res[r][0], res[r][1], res[r][2], res[r][3]));
    }
}

extern "C" void kernel_launch(void* const* d_in, const int* in_sizes, int n_in,
                              void* d_out, int out_size) {
    const float* x  = (const float*)d_in[0];
    const float* W0 = (const float*)d_in[1];
    const float* b0 = (const float*)d_in[2];
    const float* W1 = (const float*)d_in[3];
    const float* b1 = (const float*)d_in[4];
    const float* W2 = (const float*)d_in[5];
    const float* b2 = (const float*)d_in[6];
    const float* W3 = (const float*)d_in[7];
    const float* b3 = (const float*)d_in[8];
    const float* W4 = (const float*)d_in[9];
    const float* b4 = (const float*)d_in[10];
    const float* W5 = (const float*)d_in[11];
    const float* b5 = (const float*)d_in[12];

    prep_kernel<<<1, 192>>>(W0, b0, W1, b1, W2, b2, W3, b3, W4, b4, W5, b5);

    // PDL launch: mlp_kernel may start while prep is finishing; it gates
    // itself with griddepcontrol.wait before touching g_wp.
    const float4* xv = (const float4*)x;
    float4* ov = (float4*)d_out;

    cudaLaunchConfig_t cfg = {};
    cfg.gridDim = dim3((BATCH / ROWS_PER_THREAD) / NTHREADS, 1, 1);  // 2048
    cfg.blockDim = dim3(NTHREADS, 1, 1);
    cfg.dynamicSmemBytes = 0;
    cfg.stream = 0;
    cudaLaunchAttribute attr[1];
    attr[0].id = cudaLaunchAttributeProgrammaticStreamSerialization;
    attr[0].val.programmaticStreamSerializationAllowed = 1;
    cfg.attrs = attr;
    cfg.numAttrs = 1;
    cudaLaunchKernelEx(&cfg, mlp_kernel, xv, ov);
}